// round 13
// baseline (speedup 1.0000x reference)
#include <cuda_runtime.h>
#include <cuda_bf16.h>
#include <cuda_fp16.h>
#include <cuda_fp8.h>
#include <cuda_fp4.h>
#include <cstdint>

#define N_ROWS      12288        // L1_INPUT_SIZE
#define N_COLS      1030         // L1_OUTPUT_SIZE
#define HID         1024
#define BATCH       8192
#define NFEAT       32
#define L2IN        2048
#define W_SCALE     128.0f       // psqt e4m3 scale
#define INV_SCALE   0.0078125f   // 1/128
#define PSQT_K      0.08f        // 0.5 / (400/64)

// fp4(e2m1) hidden weights, per-row scaled: 512 B per row (power-of-2 stride)
__device__ __align__(128) unsigned char g_W1f4[(size_t)N_ROWS * 512];
// aux per row: bytes 0..5 = psqt e4m3 (W1*128), bytes 6..7 = row scale (half)
__device__ __align__(8)  unsigned char g_aux8[(size_t)N_ROWS * 8];

// ---------------------------------------------------------------------------
// e2m1 encoder (round-to-nearest on the grid {0,.5,1,1.5,2,3,4,6}; u pre-scaled)
// ---------------------------------------------------------------------------
__device__ __forceinline__ unsigned enc_e2m1(float u) {
    const float a = fabsf(u);
    unsigned c;
    if      (a < 0.25f) c = 0;
    else if (a < 0.75f) c = 1;
    else if (a < 1.25f) c = 2;
    else if (a < 1.75f) c = 3;
    else if (a < 2.5f)  c = 4;
    else if (a < 3.5f)  c = 5;
    else if (a < 5.0f)  c = 6;
    else                c = 7;
    return c | ((__float_as_uint(u) >> 28) & 8u);   // sign -> bit 3
}

// ---------------------------------------------------------------------------
// convert: one warp per table row. Row-max -> scale, quantize 1024 hidden
// cols to e2m1, stage in smem, coalesced uint4 stores. Psqt + scale -> aux.
// ---------------------------------------------------------------------------
__global__ __launch_bounds__(128)
void convert_kernel(const float* __restrict__ W1) {
    __shared__ __align__(16) unsigned short stage[4][256];  // 512B per warp

    const int gw  = (blockIdx.x * blockDim.x + threadIdx.x) >> 5;
    if (gw >= N_ROWS) return;
    const int L   = threadIdx.x & 31;
    const int w   = (threadIdx.x >> 5) & 3;
    const float* src = W1 + (size_t)gw * N_COLS;

    // lane L handles cols {4L+128j .. 4L+3+128j}, j = 0..7
    float vals[32];
    float amax = 0.f;
#pragma unroll
    for (int j = 0; j < 8; ++j) {
        const float* p = src + 4 * L + 128 * j;
        const float2 a = *reinterpret_cast<const float2*>(p);
        const float2 b = *reinterpret_cast<const float2*>(p + 2);
        vals[4 * j + 0] = a.x; vals[4 * j + 1] = a.y;
        vals[4 * j + 2] = b.x; vals[4 * j + 3] = b.y;
        amax = fmaxf(amax, fmaxf(fmaxf(fabsf(a.x), fabsf(a.y)),
                                 fmaxf(fabsf(b.x), fabsf(b.y))));
    }
#pragma unroll
    for (int o = 16; o > 0; o >>= 1)
        amax = fmaxf(amax, __shfl_xor_sync(0xffffffffu, amax, o));
    amax = fmaxf(amax, 1e-30f);
    const float scale = amax * (1.f / 6.f);
    const float inv   = 6.f / amax;

    // ushort index i = L + 32j covers cols 4i..4i+3 (low nibble = even col)
#pragma unroll
    for (int j = 0; j < 8; ++j) {
        const unsigned c0 = enc_e2m1(vals[4 * j + 0] * inv);
        const unsigned c1 = enc_e2m1(vals[4 * j + 1] * inv);
        const unsigned c2 = enc_e2m1(vals[4 * j + 2] * inv);
        const unsigned c3 = enc_e2m1(vals[4 * j + 3] * inv);
        stage[w][L + 32 * j] =
            (unsigned short)((c0 | (c1 << 4)) | ((c2 | (c3 << 4)) << 8));
    }
    __syncwarp();
    const uint4 outv = *reinterpret_cast<const uint4*>(&stage[w][L * 8]);
    *reinterpret_cast<uint4*>(g_W1f4 + (size_t)gw * 512 + L * 16) = outv;

    if (L < 6) {
        const float pw = src[HID + L] * W_SCALE;
        g_aux8[gw * 8 + L] =
            (unsigned char)__nv_cvt_float_to_fp8(pw, __NV_SATFINITE, __NV_E4M3);
    } else if (L == 6) {
        *reinterpret_cast<__half*>(g_aux8 + gw * 8 + 6) = __float2half_rn(scale);
    }
}

// ---------------------------------------------------------------------------
// decode u32 (8×e2m1) via HW cvt and accumulate into 4 half2 with vh
// ---------------------------------------------------------------------------
__device__ __forceinline__ void fma8_fp4(half2* acc, uint32_t wv, half2 vh) {
    __half2_raw h0 = __nv_cvt_fp4x2_to_halfraw2(
        (__nv_fp4x2_storage_t)(wv & 0xFFu), __NV_E2M1);
    __half2_raw h1 = __nv_cvt_fp4x2_to_halfraw2(
        (__nv_fp4x2_storage_t)((wv >> 8) & 0xFFu), __NV_E2M1);
    __half2_raw h2 = __nv_cvt_fp4x2_to_halfraw2(
        (__nv_fp4x2_storage_t)((wv >> 16) & 0xFFu), __NV_E2M1);
    __half2_raw h3 = __nv_cvt_fp4x2_to_halfraw2(
        (__nv_fp4x2_storage_t)(wv >> 24), __NV_E2M1);
    acc[0] = __hfma2(*reinterpret_cast<half2*>(&h0), vh, acc[0]);
    acc[1] = __hfma2(*reinterpret_cast<half2*>(&h1), vh, acc[1]);
    acc[2] = __hfma2(*reinterpret_cast<half2*>(&h2), vh, acc[2]);
    acc[3] = __hfma2(*reinterpret_cast<half2*>(&h3), vh, acc[3]);
}

// ---------------------------------------------------------------------------
// Main fused kernel: one CTA per batch row, 128 threads, 8 cols/thread/side,
// 4-deep u32 prefetch. Row scales folded into vh; psqt from aux table.
// ---------------------------------------------------------------------------
__global__ __launch_bounds__(128)
void fwd_kernel(const int*   __restrict__ x,
                const int*   __restrict__ y,
                const float* __restrict__ v,
                const int*   __restrict__ s,
                const float* __restrict__ b1,
                const float* __restrict__ W2,
                const float* __restrict__ b2,
                float*       __restrict__ out)
{
    __shared__ uint4 srec[NFEAT + 4];  // {offx, vhx_bits, offy, vhy_bits}; +4 pad
    __shared__ float spq[64];          // psqt partials
    __shared__ int   ss_sh;
    __shared__ float red[4];

    const int b = blockIdx.x;
    const int t = threadIdx.x;

    if (t < 64) {
        const int side = t >> 5;
        const int a    = t & 31;
        const int gi   = b * NFEAT + a;
        const int idx  = side ? y[gi] : x[gi];
        const float vv = v[gi];
        const int ss   = s[b];
        const uint2 aux = *reinterpret_cast<const uint2*>(g_aux8 + idx * 8);
        const unsigned short shb = (unsigned short)(aux.y >> 16);
        const float scale = __half2float(*reinterpret_cast<const __half*>(&shb));
        const half2 vh = __float2half2_rn(vv * scale);
        const unsigned vhbits = *reinterpret_cast<const unsigned*>(&vh);
        if (side == 0) { srec[a].x = (unsigned)(idx * 512); srec[a].y = vhbits; }
        else           { srec[a].z = (unsigned)(idx * 512); srec[a].w = vhbits; }
        // psqt partial from aux byte ss (bytes 0..5)
        unsigned bytev = (ss < 4) ? (aux.x >> (8 * ss)) : (aux.y >> (8 * (ss - 4)));
        bytev &= 0xFFu;
        const float wgt = __half2float(
            __nv_cvt_fp8_to_halfraw((__nv_fp8_storage_t)bytev, __NV_E4M3));
        const float p = vv * wgt * (PSQT_K * INV_SCALE);
        spq[t] = side ? -p : p;
    } else if (t < 68) {
        srec[NFEAT + t - 64] = make_uint4(0, 0, 0, 0);
    } else if (t == 68) {
        ss_sh = s[b];
    }
    __syncthreads();

    const unsigned char* basep = g_W1f4 + t * 4;   // this thread's 8 fp4 columns

    // ---- prime the 4-deep prefetch pipeline ----
    uint32_t px[4], py[4];
#pragma unroll
    for (int i = 0; i < 4; ++i) {
        const uint4 R = srec[i];
        px[i] = *reinterpret_cast<const uint32_t*>(basep + R.x);
        py[i] = *reinterpret_cast<const uint32_t*>(basep + R.z);
    }

    half2 ax[4], ay[4];
#pragma unroll
    for (int j = 0; j < 4; ++j) { ax[j] = __float2half2_rn(0.f); ay[j] = __float2half2_rn(0.f); }

#pragma unroll 4
    for (int a = 0; a < NFEAT; ++a) {
        const int slot = a & 3;
        const uint32_t wx = px[slot];
        const uint32_t wy = py[slot];
        const uint4 R  = srec[a];          // vh bits for this feature
        const uint4 Rn = srec[a + 4];      // next offsets
        px[slot] = *reinterpret_cast<const uint32_t*>(basep + Rn.x);
        py[slot] = *reinterpret_cast<const uint32_t*>(basep + Rn.z);

        half2 vhx; *reinterpret_cast<unsigned*>(&vhx) = R.y;
        half2 vhy; *reinterpret_cast<unsigned*>(&vhy) = R.w;
        fma8_fp4(ax, wx, vhx);
        fma8_fp4(ay, wy, vhy);
    }

    // ---- epilogue: relu(acc + b1) dot W2[ss] (scales already folded) ----
    const int ss = ss_sh;
    const int col0 = t * 8;
    const float4 b1a = *reinterpret_cast<const float4*>(b1 + col0);
    const float4 b1b = *reinterpret_cast<const float4*>(b1 + col0 + 4);
    const float* w2row = W2 + (size_t)ss * L2IN;
    const float4 wxa = *reinterpret_cast<const float4*>(w2row + col0);
    const float4 wxb = *reinterpret_cast<const float4*>(w2row + col0 + 4);
    const float4 wya = *reinterpret_cast<const float4*>(w2row + HID + col0);
    const float4 wyb = *reinterpret_cast<const float4*>(w2row + HID + col0 + 4);

    const float2 fx0 = __half22float2(ax[0]);
    const float2 fx1 = __half22float2(ax[1]);
    const float2 fx2 = __half22float2(ax[2]);
    const float2 fx3 = __half22float2(ax[3]);
    const float2 fy0 = __half22float2(ay[0]);
    const float2 fy1 = __half22float2(ay[1]);
    const float2 fy2 = __half22float2(ay[2]);
    const float2 fy3 = __half22float2(ay[3]);

    float local = 0.f;
    local = fmaf(fmaxf(fx0.x + b1a.x, 0.f), wxa.x, local);
    local = fmaf(fmaxf(fx0.y + b1a.y, 0.f), wxa.y, local);
    local = fmaf(fmaxf(fx1.x + b1a.z, 0.f), wxa.z, local);
    local = fmaf(fmaxf(fx1.y + b1a.w, 0.f), wxa.w, local);
    local = fmaf(fmaxf(fx2.x + b1b.x, 0.f), wxb.x, local);
    local = fmaf(fmaxf(fx2.y + b1b.y, 0.f), wxb.y, local);
    local = fmaf(fmaxf(fx3.x + b1b.z, 0.f), wxb.z, local);
    local = fmaf(fmaxf(fx3.y + b1b.w, 0.f), wxb.w, local);

    local = fmaf(fmaxf(fy0.x + b1a.x, 0.f), wya.x, local);
    local = fmaf(fmaxf(fy0.y + b1a.y, 0.f), wya.y, local);
    local = fmaf(fmaxf(fy1.x + b1a.z, 0.f), wya.z, local);
    local = fmaf(fmaxf(fy1.y + b1a.w, 0.f), wya.w, local);
    local = fmaf(fmaxf(fy2.x + b1b.x, 0.f), wyb.x, local);
    local = fmaf(fmaxf(fy2.y + b1b.y, 0.f), wyb.y, local);
    local = fmaf(fmaxf(fy3.x + b1b.z, 0.f), wyb.z, local);
    local = fmaf(fmaxf(fy3.y + b1b.w, 0.f), wyb.w, local);

    // ---- psqt partial (precomputed in prologue) ----
    if (t < 64) local += spq[t];

    // ---- block reduction ----
#pragma unroll
    for (int o = 16; o > 0; o >>= 1)
        local += __shfl_down_sync(0xffffffffu, local, o);
    if ((t & 31) == 0) red[t >> 5] = local;
    __syncthreads();
    if (t == 0) {
        const float c = red[0] + red[1] + red[2] + red[3] + b2[ss];
        out[b] = 1.0f / (1.0f + expf(-c));
    }
}

// ---------------------------------------------------------------------------
extern "C" void kernel_launch(void* const* d_in, const int* in_sizes, int n_in,
                              void* d_out, int out_size)
{
    const int*   x  = (const int*)  d_in[0];
    const int*   y  = (const int*)  d_in[1];
    const float* v  = (const float*)d_in[2];
    const int*   s  = (const int*)  d_in[3];
    const float* W1 = (const float*)d_in[4];
    const float* b1 = (const float*)d_in[5];
    const float* W2 = (const float*)d_in[6];
    const float* b2 = (const float*)d_in[7];
    float* out = (float*)d_out;

    convert_kernel<<<N_ROWS / 4, 128>>>(W1);
    fwd_kernel<<<BATCH, 128>>>(x, y, v, s, b1, W2, b2, out);
}

// round 14
// speedup vs baseline: 1.5294x; 1.5294x over previous
#include <cuda_runtime.h>
#include <cuda_bf16.h>
#include <cuda_fp16.h>
#include <cuda_fp8.h>
#include <cstdint>

#define N_ROWS      12288        // L1_INPUT_SIZE
#define N_COLS      1030         // L1_OUTPUT_SIZE
#define HID         1024
#define STRIDE8     1040         // padded fp8 row stride bytes (16B multiple)
#define BATCH       8192
#define NFEAT       32
#define L2IN        2048
#define W_SCALE     128.0f       // weight scale into e4m3 normal range
#define INV_SCALE   0.0078125f   // 1/128
#define PSQT_K      0.08f        // 0.5 / (400/64)
#define GPR         260          // groups of 4 cols per row (260*4 = 1040)

// fp8(e4m3) copy of W1*128 (module-static, no runtime alloc)
__device__ __align__(128) unsigned char g_W1f8[(size_t)N_ROWS * STRIDE8];

// ---------------------------------------------------------------------------
// W1 fp32 -> fp8 conversion (R2-proven shape: u32 store per thread)
// ---------------------------------------------------------------------------
__global__ void convert_kernel(const float* __restrict__ W1) {
    int gid = blockIdx.x * blockDim.x + threadIdx.x;
    if (gid >= N_ROWS * GPR) return;
    const int r   = gid / GPR;
    const int g   = gid - r * GPR;
    const int col = g * 4;
    const float* src = W1 + (size_t)r * N_COLS + col;

    float4 w;
    if (col + 4 <= N_COLS) {
        const float2 a = *reinterpret_cast<const float2*>(src);
        const float2 b = *reinterpret_cast<const float2*>(src + 2);
        w = make_float4(a.x, a.y, b.x, b.y);
    } else {
        w.x = (col + 0 < N_COLS) ? src[0] : 0.f;
        w.y = (col + 1 < N_COLS) ? src[1] : 0.f;
        w.z = (col + 2 < N_COLS) ? src[2] : 0.f;
        w.w = (col + 3 < N_COLS) ? src[3] : 0.f;
    }
    const __nv_fp8x2_storage_t lo =
        __nv_cvt_float2_to_fp8x2(make_float2(w.x * W_SCALE, w.y * W_SCALE),
                                 __NV_SATFINITE, __NV_E4M3);
    const __nv_fp8x2_storage_t hi =
        __nv_cvt_float2_to_fp8x2(make_float2(w.z * W_SCALE, w.w * W_SCALE),
                                 __NV_SATFINITE, __NV_E4M3);
    const uint32_t packed = (uint32_t)lo | ((uint32_t)hi << 16);
    *reinterpret_cast<uint32_t*>(g_W1f8 + (size_t)r * STRIDE8 + col) = packed;
}

// ---------------------------------------------------------------------------
// unpack u32 (4×e4m3) -> two half2, fused multiply-accumulate with vh
// ---------------------------------------------------------------------------
__device__ __forceinline__ void fma4_fp8(half2& a0, half2& a1, uint32_t w, half2 vh) {
    uint32_t h0, h1;
    asm("{\n\t"
        ".reg .b16 lo, hi;\n\t"
        "mov.b32 {lo, hi}, %2;\n\t"
        "cvt.rn.f16x2.e4m3x2 %0, lo;\n\t"
        "cvt.rn.f16x2.e4m3x2 %1, hi;\n\t"
        "}" : "=r"(h0), "=r"(h1) : "r"(w));
    a0 = __hfma2(*reinterpret_cast<half2*>(&h0), vh, a0);
    a1 = __hfma2(*reinterpret_cast<half2*>(&h1), vh, a1);
}

// ---------------------------------------------------------------------------
// Main fused kernel: one CTA per batch row, 128 threads, 8 cols/thread/side,
// 4-deep register prefetch (8 LDG.64 in flight/warp), packed uint4 records.
// ---------------------------------------------------------------------------
__global__ __launch_bounds__(128)
void fwd_kernel(const int*   __restrict__ x,
                const int*   __restrict__ y,
                const float* __restrict__ v,
                const int*   __restrict__ s,
                const float* __restrict__ b1,
                const float* __restrict__ W2,
                const float* __restrict__ b2,
                float*       __restrict__ out)
{
    __shared__ uint4 srec[NFEAT + 4];  // {offx, offy, vh_bits, vf_bits}; +4 pad
    __shared__ int   ss_sh;
    __shared__ float red[4];

    const int b = blockIdx.x;
    const int t = threadIdx.x;

    if (t < NFEAT) {
        const int gi = b * NFEAT + t;
        const float vv = v[gi];
        const half2 vh = __float2half2_rn(vv);
        srec[t] = make_uint4((unsigned)(x[gi] * STRIDE8),
                             (unsigned)(y[gi] * STRIDE8),
                             *reinterpret_cast<const unsigned*>(&vh),
                             __float_as_uint(vv));
    } else if (t < NFEAT + 4) {        // pad so tail prefetches stay in-bounds
        srec[t] = make_uint4(0, 0, 0, 0);
    } else if (t == 64) {
        ss_sh = s[b];
    }
    __syncthreads();

    const unsigned char* basep = g_W1f8 + t * 8;   // this thread's 8 fp8 columns

    // ---- prime the 4-deep prefetch pipeline ----
    uint2 px[4], py[4];
#pragma unroll
    for (int i = 0; i < 4; ++i) {
        const uint4 R = srec[i];
        px[i] = *reinterpret_cast<const uint2*>(basep + R.x);
        py[i] = *reinterpret_cast<const uint2*>(basep + R.y);
    }

    half2 ax[4], ay[4];
#pragma unroll
    for (int j = 0; j < 4; ++j) { ax[j] = __float2half2_rn(0.f); ay[j] = __float2half2_rn(0.f); }

#pragma unroll 8
    for (int a = 0; a < NFEAT; ++a) {
        const int slot = a & 3;
        const uint2 wx = px[slot];
        const uint2 wy = py[slot];
        const uint4 R  = srec[a];          // vh bits for this feature
        const uint4 Rn = srec[a + 4];      // next offsets (one LDS.128 each)
        px[slot] = *reinterpret_cast<const uint2*>(basep + Rn.x);
        py[slot] = *reinterpret_cast<const uint2*>(basep + Rn.y);

        half2 vh; *reinterpret_cast<uint32_t*>(&vh) = R.z;
        fma4_fp8(ax[0], ax[1], wx.x, vh);
        fma4_fp8(ax[2], ax[3], wx.y, vh);
        fma4_fp8(ay[0], ay[1], wy.x, vh);
        fma4_fp8(ay[2], ay[3], wy.y, vh);
    }

    // ---- epilogue: relu(acc/128 + b1) dot W2[ss] ----
    const int ss = ss_sh;
    const int col0 = t * 8;
    const float4 b1a = *reinterpret_cast<const float4*>(b1 + col0);
    const float4 b1b = *reinterpret_cast<const float4*>(b1 + col0 + 4);
    const float* w2row = W2 + (size_t)ss * L2IN;
    const float4 wxa = *reinterpret_cast<const float4*>(w2row + col0);
    const float4 wxb = *reinterpret_cast<const float4*>(w2row + col0 + 4);
    const float4 wya = *reinterpret_cast<const float4*>(w2row + HID + col0);
    const float4 wyb = *reinterpret_cast<const float4*>(w2row + HID + col0 + 4);

    const float2 fx0 = __half22float2(ax[0]);
    const float2 fx1 = __half22float2(ax[1]);
    const float2 fx2 = __half22float2(ax[2]);
    const float2 fx3 = __half22float2(ax[3]);
    const float2 fy0 = __half22float2(ay[0]);
    const float2 fy1 = __half22float2(ay[1]);
    const float2 fy2 = __half22float2(ay[2]);
    const float2 fy3 = __half22float2(ay[3]);

    float local = 0.f;
    local = fmaf(fmaxf(fmaf(fx0.x, INV_SCALE, b1a.x), 0.f), wxa.x, local);
    local = fmaf(fmaxf(fmaf(fx0.y, INV_SCALE, b1a.y), 0.f), wxa.y, local);
    local = fmaf(fmaxf(fmaf(fx1.x, INV_SCALE, b1a.z), 0.f), wxa.z, local);
    local = fmaf(fmaxf(fmaf(fx1.y, INV_SCALE, b1a.w), 0.f), wxa.w, local);
    local = fmaf(fmaxf(fmaf(fx2.x, INV_SCALE, b1b.x), 0.f), wxb.x, local);
    local = fmaf(fmaxf(fmaf(fx2.y, INV_SCALE, b1b.y), 0.f), wxb.y, local);
    local = fmaf(fmaxf(fmaf(fx3.x, INV_SCALE, b1b.z), 0.f), wxb.z, local);
    local = fmaf(fmaxf(fmaf(fx3.y, INV_SCALE, b1b.w), 0.f), wxb.w, local);

    local = fmaf(fmaxf(fmaf(fy0.x, INV_SCALE, b1a.x), 0.f), wya.x, local);
    local = fmaf(fmaxf(fmaf(fy0.y, INV_SCALE, b1a.y), 0.f), wya.y, local);
    local = fmaf(fmaxf(fmaf(fy1.x, INV_SCALE, b1a.z), 0.f), wya.z, local);
    local = fmaf(fmaxf(fmaf(fy1.y, INV_SCALE, b1a.w), 0.f), wya.w, local);
    local = fmaf(fmaxf(fmaf(fy2.x, INV_SCALE, b1b.x), 0.f), wyb.x, local);
    local = fmaf(fmaxf(fmaf(fy2.y, INV_SCALE, b1b.y), 0.f), wyb.y, local);
    local = fmaf(fmaxf(fmaf(fy3.x, INV_SCALE, b1b.z), 0.f), wyb.z, local);
    local = fmaf(fmaxf(fmaf(fy3.y, INV_SCALE, b1b.w), 0.f), wyb.w, local);

    // ---- psqt term: (x2 - y2) * PSQT_K ; b1 cancels in the difference ----
    if (t < 64) {
        const int a  = t & 31;
        const int sp = t >> 5;               // 0 = x, 1 = y
        const uint4 R = srec[a];
        const unsigned off = sp ? R.y : R.x;
        const unsigned char wb = g_W1f8[(size_t)off + HID + ss];
        const float wgt = __half2float(
            __nv_cvt_fp8_to_halfraw((__nv_fp8_storage_t)wb, __NV_E4M3));
        const float p = __uint_as_float(R.w) * wgt * (PSQT_K * INV_SCALE);
        local += sp ? -p : p;
    }

    // ---- block reduction ----
#pragma unroll
    for (int o = 16; o > 0; o >>= 1)
        local += __shfl_down_sync(0xffffffffu, local, o);
    if ((t & 31) == 0) red[t >> 5] = local;
    __syncthreads();
    if (t == 0) {
        const float c = red[0] + red[1] + red[2] + red[3] + b2[ss];
        out[b] = 1.0f / (1.0f + __expf(-c));
    }
}

// ---------------------------------------------------------------------------
extern "C" void kernel_launch(void* const* d_in, const int* in_sizes, int n_in,
                              void* d_out, int out_size)
{
    const int*   x  = (const int*)  d_in[0];
    const int*   y  = (const int*)  d_in[1];
    const float* v  = (const float*)d_in[2];
    const int*   s  = (const int*)  d_in[3];
    const float* W1 = (const float*)d_in[4];
    const float* b1 = (const float*)d_in[5];
    const float* W2 = (const float*)d_in[6];
    const float* b2 = (const float*)d_in[7];
    float* out = (float*)d_out;

    const int total = N_ROWS * GPR;
    convert_kernel<<<(total + 255) / 256, 256>>>(W1);
    fwd_kernel<<<BATCH, 128>>>(x, y, v, s, b1, W2, b2, out);
}

// round 17
// speedup vs baseline: 1.5417x; 1.0080x over previous
#include <cuda_runtime.h>
#include <cuda_bf16.h>
#include <cuda_fp16.h>
#include <cuda_fp8.h>
#include <cstdint>

#define N_ROWS      12288        // L1_INPUT_SIZE
#define N_COLS      1030         // L1_OUTPUT_SIZE
#define HID         1024
#define STRIDE8     1152         // padded fp8 row stride bytes (9*128 -> 128B aligned rows)
#define BATCH       8192
#define NFEAT       32
#define L2IN        2048
#define W_SCALE     128.0f       // weight scale into e4m3 normal range
#define INV_SCALE   0.0078125f   // 1/128
#define PSQT_K      0.08f        // 0.5 / (400/64)
#define GPR         260          // groups of 4 cols written per row (260*4 = 1040 >= 1030)

// fp8(e4m3) copy of W1*128, 128B-aligned rows (module-static, no runtime alloc)
__device__ __align__(128) unsigned char g_W1f8[(size_t)N_ROWS * STRIDE8];

// ---------------------------------------------------------------------------
// W1 fp32 -> fp8 conversion (R2-proven shape: u32 store per thread)
// ---------------------------------------------------------------------------
__global__ void convert_kernel(const float* __restrict__ W1) {
    int gid = blockIdx.x * blockDim.x + threadIdx.x;
    if (gid >= N_ROWS * GPR) return;
    const int r   = gid / GPR;
    const int g   = gid - r * GPR;
    const int col = g * 4;
    const float* src = W1 + (size_t)r * N_COLS + col;

    float4 w;
    if (col + 4 <= N_COLS) {
        const float2 a = *reinterpret_cast<const float2*>(src);
        const float2 b = *reinterpret_cast<const float2*>(src + 2);
        w = make_float4(a.x, a.y, b.x, b.y);
    } else {
        w.x = (col + 0 < N_COLS) ? src[0] : 0.f;
        w.y = (col + 1 < N_COLS) ? src[1] : 0.f;
        w.z = (col + 2 < N_COLS) ? src[2] : 0.f;
        w.w = (col + 3 < N_COLS) ? src[3] : 0.f;
    }
    const __nv_fp8x2_storage_t lo =
        __nv_cvt_float2_to_fp8x2(make_float2(w.x * W_SCALE, w.y * W_SCALE),
                                 __NV_SATFINITE, __NV_E4M3);
    const __nv_fp8x2_storage_t hi =
        __nv_cvt_float2_to_fp8x2(make_float2(w.z * W_SCALE, w.w * W_SCALE),
                                 __NV_SATFINITE, __NV_E4M3);
    const uint32_t packed = (uint32_t)lo | ((uint32_t)hi << 16);
    *reinterpret_cast<uint32_t*>(g_W1f8 + (size_t)r * STRIDE8 + col) = packed;
}

// ---------------------------------------------------------------------------
// unpack u32 (4×e4m3) -> two half2, fused multiply-accumulate with vh
// ---------------------------------------------------------------------------
__device__ __forceinline__ void fma4_fp8(half2& a0, half2& a1, uint32_t w, half2 vh) {
    uint32_t h0, h1;
    asm("{\n\t"
        ".reg .b16 lo, hi;\n\t"
        "mov.b32 {lo, hi}, %2;\n\t"
        "cvt.rn.f16x2.e4m3x2 %0, lo;\n\t"
        "cvt.rn.f16x2.e4m3x2 %1, hi;\n\t"
        "}" : "=r"(h0), "=r"(h1) : "r"(w));
    a0 = __hfma2(*reinterpret_cast<half2*>(&h0), vh, a0);
    a1 = __hfma2(*reinterpret_cast<half2*>(&h1), vh, a1);
}

// ---------------------------------------------------------------------------
// Main fused kernel: one CTA per batch row, 128 threads, 8 cols/thread/side,
// 4-deep register prefetch (8 LDG.64 in flight/warp), packed uint4 records.
// Rows 128B-aligned: every warp gather-load touches exactly 2 L1 lines.
// ---------------------------------------------------------------------------
__global__ __launch_bounds__(128)
void fwd_kernel(const int*   __restrict__ x,
                const int*   __restrict__ y,
                const float* __restrict__ v,
                const int*   __restrict__ s,
                const float* __restrict__ b1,
                const float* __restrict__ W2,
                const float* __restrict__ b2,
                float*       __restrict__ out)
{
    __shared__ uint4 srec[NFEAT + 4];  // {offx, offy, vh_bits, vf_bits}; +4 pad
    __shared__ int   ss_sh;
    __shared__ float red[4];

    const int b = blockIdx.x;
    const int t = threadIdx.x;

    if (t < NFEAT) {
        const int gi = b * NFEAT + t;
        const float vv = v[gi];
        const half2 vh = __float2half2_rn(vv);
        srec[t] = make_uint4((unsigned)(x[gi] * STRIDE8),
                             (unsigned)(y[gi] * STRIDE8),
                             *reinterpret_cast<const unsigned*>(&vh),
                             __float_as_uint(vv));
    } else if (t < NFEAT + 4) {        // pad so tail prefetches stay in-bounds
        srec[t] = make_uint4(0, 0, 0, 0);
    } else if (t == 64) {
        ss_sh = s[b];
    }
    __syncthreads();

    const unsigned char* basep = g_W1f8 + t * 8;   // this thread's 8 fp8 columns

    // ---- prime the 4-deep prefetch pipeline ----
    uint2 px[4], py[4];
#pragma unroll
    for (int i = 0; i < 4; ++i) {
        const uint4 R = srec[i];
        px[i] = *reinterpret_cast<const uint2*>(basep + R.x);
        py[i] = *reinterpret_cast<const uint2*>(basep + R.y);
    }

    half2 ax[4], ay[4];
#pragma unroll
    for (int j = 0; j < 4; ++j) { ax[j] = __float2half2_rn(0.f); ay[j] = __float2half2_rn(0.f); }

#pragma unroll 8
    for (int a = 0; a < NFEAT; ++a) {
        const int slot = a & 3;
        const uint2 wx = px[slot];
        const uint2 wy = py[slot];
        const uint4 R  = srec[a];          // vh bits for this feature
        const uint4 Rn = srec[a + 4];      // next offsets (one LDS.128 each)
        px[slot] = *reinterpret_cast<const uint2*>(basep + Rn.x);
        py[slot] = *reinterpret_cast<const uint2*>(basep + Rn.y);

        half2 vh; *reinterpret_cast<uint32_t*>(&vh) = R.z;
        fma4_fp8(ax[0], ax[1], wx.x, vh);
        fma4_fp8(ax[2], ax[3], wx.y, vh);
        fma4_fp8(ay[0], ay[1], wy.x, vh);
        fma4_fp8(ay[2], ay[3], wy.y, vh);
    }

    // ---- epilogue: relu(acc/128 + b1) dot W2[ss] ----
    const int ss = ss_sh;
    const int col0 = t * 8;
    const float4 b1a = *reinterpret_cast<const float4*>(b1 + col0);
    const float4 b1b = *reinterpret_cast<const float4*>(b1 + col0 + 4);
    const float* w2row = W2 + (size_t)ss * L2IN;
    const float4 wxa = *reinterpret_cast<const float4*>(w2row + col0);
    const float4 wxb = *reinterpret_cast<const float4*>(w2row + col0 + 4);
    const float4 wya = *reinterpret_cast<const float4*>(w2row + HID + col0);
    const float4 wyb = *reinterpret_cast<const float4*>(w2row + HID + col0 + 4);

    const float2 fx0 = __half22float2(ax[0]);
    const float2 fx1 = __half22float2(ax[1]);
    const float2 fx2 = __half22float2(ax[2]);
    const float2 fx3 = __half22float2(ax[3]);
    const float2 fy0 = __half22float2(ay[0]);
    const float2 fy1 = __half22float2(ay[1]);
    const float2 fy2 = __half22float2(ay[2]);
    const float2 fy3 = __half22float2(ay[3]);

    float local = 0.f;
    local = fmaf(fmaxf(fmaf(fx0.x, INV_SCALE, b1a.x), 0.f), wxa.x, local);
    local = fmaf(fmaxf(fmaf(fx0.y, INV_SCALE, b1a.y), 0.f), wxa.y, local);
    local = fmaf(fmaxf(fmaf(fx1.x, INV_SCALE, b1a.z), 0.f), wxa.z, local);
    local = fmaf(fmaxf(fmaf(fx1.y, INV_SCALE, b1a.w), 0.f), wxa.w, local);
    local = fmaf(fmaxf(fmaf(fx2.x, INV_SCALE, b1b.x), 0.f), wxb.x, local);
    local = fmaf(fmaxf(fmaf(fx2.y, INV_SCALE, b1b.y), 0.f), wxb.y, local);
    local = fmaf(fmaxf(fmaf(fx3.x, INV_SCALE, b1b.z), 0.f), wxb.z, local);
    local = fmaf(fmaxf(fmaf(fx3.y, INV_SCALE, b1b.w), 0.f), wxb.w, local);

    local = fmaf(fmaxf(fmaf(fy0.x, INV_SCALE, b1a.x), 0.f), wya.x, local);
    local = fmaf(fmaxf(fmaf(fy0.y, INV_SCALE, b1a.y), 0.f), wya.y, local);
    local = fmaf(fmaxf(fmaf(fy1.x, INV_SCALE, b1a.z), 0.f), wya.z, local);
    local = fmaf(fmaxf(fmaf(fy1.y, INV_SCALE, b1a.w), 0.f), wya.w, local);
    local = fmaf(fmaxf(fmaf(fy2.x, INV_SCALE, b1b.x), 0.f), wyb.x, local);
    local = fmaf(fmaxf(fmaf(fy2.y, INV_SCALE, b1b.y), 0.f), wyb.y, local);
    local = fmaf(fmaxf(fmaf(fy3.x, INV_SCALE, b1b.z), 0.f), wyb.z, local);
    local = fmaf(fmaxf(fmaf(fy3.y, INV_SCALE, b1b.w), 0.f), wyb.w, local);

    // ---- psqt term: (x2 - y2) * PSQT_K ; b1 cancels in the difference ----
    if (t < 64) {
        const int a  = t & 31;
        const int sp = t >> 5;               // 0 = x, 1 = y
        const uint4 R = srec[a];
        const unsigned off = sp ? R.y : R.x;
        const unsigned char wb = g_W1f8[(size_t)off + HID + ss];
        const float wgt = __half2float(
            __nv_cvt_fp8_to_halfraw((__nv_fp8_storage_t)wb, __NV_E4M3));
        const float p = __uint_as_float(R.w) * wgt * (PSQT_K * INV_SCALE);
        local += sp ? -p : p;
    }

    // ---- block reduction ----
#pragma unroll
    for (int o = 16; o > 0; o >>= 1)
        local += __shfl_down_sync(0xffffffffu, local, o);
    if ((t & 31) == 0) red[t >> 5] = local;
    __syncthreads();
    if (t == 0) {
        const float c = red[0] + red[1] + red[2] + red[3] + b2[ss];
        out[b] = 1.0f / (1.0f + __expf(-c));
    }
}

// ---------------------------------------------------------------------------
extern "C" void kernel_launch(void* const* d_in, const int* in_sizes, int n_in,
                              void* d_out, int out_size)
{
    const int*   x  = (const int*)  d_in[0];
    const int*   y  = (const int*)  d_in[1];
    const float* v  = (const float*)d_in[2];
    const int*   s  = (const int*)  d_in[3];
    const float* W1 = (const float*)d_in[4];
    const float* b1 = (const float*)d_in[5];
    const float* W2 = (const float*)d_in[6];
    const float* b2 = (const float*)d_in[7];
    float* out = (float*)d_out;

    const int total = N_ROWS * GPR;
    convert_kernel<<<(total + 255) / 256, 256>>>(W1);
    fwd_kernel<<<BATCH, 128>>>(x, y, v, s, b1, W2, b2, out);
}